// round 8
// baseline (speedup 1.0000x reference)
#include <cuda_runtime.h>
#include <cuda_bf16.h>

// ---------------------------------------------------------------------------
// PointerNet additive attention, fused persistent kernel with warp
// specialization + per-source-block dependency tracking.
// B=4, Te=Td=512, E=256, D+E=512, H=64.
// out[b,d,t] = softmax_t( sum_h w2[h]*tanh(dec_t[b,d,h] + ctx_t[b,t,h]) )
//
// grid = 148 x 1024. Block (b,ti) owns decoder rows [14ti,14ti+14) AND
// produces ctxT columns t in [14ti,14ti+14).
//   1) all warps: load tiles, ctx projection -> g_ctxT,
//      release g_done[b*37+ti] (generation counter, graph-replay safe)
//   2) warps 16-31: dec projection in four 16-h chunks -> dec_sh
//      (bar.arrive publish) -- overlaps consumers' MUFU work
//   3) warps 0-15: each LANE acquire-spins only on its own source block's
//      flag (t/14), then tanh.approx score + softmax
// ---------------------------------------------------------------------------

#define LOG2E 1.4426950408889634f

__device__ float    g_ctxT[4 * 64 * 512];   // [b][h][t]
__device__ unsigned g_startc[4];            // per-batch start tickets
__device__ unsigned g_done[4 * 37];         // per-block generation flags

// dynamic smem layout (floats)
#define CT_OFF 0          // ctx tile  14x256 = 3584
#define DT_OFF 3584       // dec tile  14x512 = 7168
#define P_OFF  10752      // ctx partials 16x952 = 15232 (reused: dec chunks)
#define SM_FLOATS (P_OFF + 16 * 952)   // 25984 floats = 103936 B

__device__ __forceinline__ float ex2_approx(float x) {
    float y; asm("ex2.approx.f32 %0, %1;" : "=f"(y) : "f"(x)); return y;
}
__device__ __forceinline__ float tanh_approx(float x) {
    float y; asm("tanh.approx.f32 %0, %1;" : "=f"(y) : "f"(x)); return y;
}
__device__ __forceinline__ void bar_sync(int id, int cnt) {
    asm volatile("bar.sync %0, %1;" :: "r"(id), "r"(cnt) : "memory");
}
__device__ __forceinline__ void bar_arrive(int id, int cnt) {
    asm volatile("bar.arrive %0, %1;" :: "r"(id), "r"(cnt) : "memory");
}
__device__ __forceinline__ unsigned ld_acquire(const unsigned* p) {
    unsigned v;
    asm volatile("ld.acquire.gpu.global.u32 %0, [%1];" : "=r"(v) : "l"(p) : "memory");
    return v;
}
__device__ __forceinline__ void red_release_add(unsigned* p, unsigned v) {
    asm volatile("red.release.gpu.global.add.u32 [%0], %1;" :: "l"(p), "r"(v) : "memory");
}

__global__ __launch_bounds__(1024, 1) void fused_kernel(
    const float* __restrict__ ctx,   // [4,512,256]
    const float* __restrict__ dec,   // [4,512,512]
    const float* __restrict__ W1i,   // [256,64]
    const float* __restrict__ b1i,   // [64]
    const float* __restrict__ W1h,   // [512,64]
    const float* __restrict__ b1h,   // [64]
    const float* __restrict__ w2,    // [64]
    float* __restrict__ out)         // [4,512,512]
{
    extern __shared__ __align__(16) float sm[];
    __shared__ __align__(16) float dec_sh[896];   // 14 rows x 64 h
    __shared__ __align__(16) float w2_sh[64];     // pre-scaled by log2e
    __shared__ float red[224];                    // 14 d x 16 warp-partials
    __shared__ float inv_sh[14];
    __shared__ unsigned gen_sh;                   // this run's generation

    const int tid  = threadIdx.x;
    const int wid  = tid >> 5;
    const int lane = tid & 31;
    const int b    = blockIdx.x / 37;
    const int ti   = blockIdx.x % 37;
    const int d0   = ti * 14;

    // ctx-proj work decomposition (used below)
    const int es   = wid & 15;                    // e-group (16-way)
    const int rg   = wid >> 4;                    // row-group (2-way, 7 rows)
    const int half = lane >> 4;
    const int hq   = (lane & 15) << 2;            // h-quad base
    const int sub  = 2 * es + half;               // 0..31 e-subranges

    if (tid == 0) gen_sh = atomicAdd(&g_startc[b], 1u) / 37u;

    // =================== load both tiles + w2 (one sync) ===================
    {
        const float4* csrc = reinterpret_cast<const float4*>(ctx)
                           + ((size_t)(b << 9) + d0) * 64;
        const float4* dsrc = reinterpret_cast<const float4*>(dec)
                           + ((size_t)(b << 9) + d0) * 128;
        float4* CT4 = reinterpret_cast<float4*>(sm + CT_OFF);
        float4* DT4 = reinterpret_cast<float4*>(sm + DT_OFF);
        #pragma unroll
        for (int i = tid; i < 2688; i += 1024) {
            if (i < 896) {
                int r = i >> 6;
                CT4[i] = (d0 + r < 512) ? csrc[i] : make_float4(0.f,0.f,0.f,0.f);
            } else {
                int j = i - 896;
                int r = j >> 7;
                DT4[j] = (d0 + r < 512) ? dsrc[j] : make_float4(0.f,0.f,0.f,0.f);
            }
        }
        if (tid < 64) w2_sh[tid] = w2[tid] * LOG2E;
    }

    // prefetch ctx-proj weights (group 0) before the barrier: hides LDG
    // latency under the DRAM tile load (ptxas cannot hoist across bar.sync)
    const float* wp_c = W1i + (size_t)(sub * 8) * 64 + hq;
    float4 pw0 = *reinterpret_cast<const float4*>(wp_c + 0 * 64);
    float4 pw1 = *reinterpret_cast<const float4*>(wp_c + 1 * 64);
    float4 pw2 = *reinterpret_cast<const float4*>(wp_c + 2 * 64);
    float4 pw3 = *reinterpret_cast<const float4*>(wp_c + 3 * 64);

    __syncthreads();

    // =================== ctx projection (all 32 warps) =====================
    {
        float acc[7][4];
        #pragma unroll
        for (int r = 0; r < 7; r++)
            #pragma unroll
            for (int j = 0; j < 4; j++) acc[r][j] = 0.f;

        const float* xb = sm + CT_OFF + (rg * 7) * 256 + sub * 8;

        // ---- e-group 0 (prefetched weights) ----
        #pragma unroll
        for (int r = 0; r < 7; r++) {
            float4 x = *reinterpret_cast<const float4*>(xb + r * 256 + 0);
            acc[r][0] = fmaf(x.x, pw0.x, acc[r][0]);
            acc[r][1] = fmaf(x.x, pw0.y, acc[r][1]);
            acc[r][2] = fmaf(x.x, pw0.z, acc[r][2]);
            acc[r][3] = fmaf(x.x, pw0.w, acc[r][3]);
            acc[r][0] = fmaf(x.y, pw1.x, acc[r][0]);
            acc[r][1] = fmaf(x.y, pw1.y, acc[r][1]);
            acc[r][2] = fmaf(x.y, pw1.z, acc[r][2]);
            acc[r][3] = fmaf(x.y, pw1.w, acc[r][3]);
            acc[r][0] = fmaf(x.z, pw2.x, acc[r][0]);
            acc[r][1] = fmaf(x.z, pw2.y, acc[r][1]);
            acc[r][2] = fmaf(x.z, pw2.z, acc[r][2]);
            acc[r][3] = fmaf(x.z, pw2.w, acc[r][3]);
            acc[r][0] = fmaf(x.w, pw3.x, acc[r][0]);
            acc[r][1] = fmaf(x.w, pw3.y, acc[r][1]);
            acc[r][2] = fmaf(x.w, pw3.z, acc[r][2]);
            acc[r][3] = fmaf(x.w, pw3.w, acc[r][3]);
        }
        // ---- e-group 1 ----
        {
            float4 w0 = *reinterpret_cast<const float4*>(wp_c + 4 * 64);
            float4 w1 = *reinterpret_cast<const float4*>(wp_c + 5 * 64);
            float4 w2v = *reinterpret_cast<const float4*>(wp_c + 6 * 64);
            float4 w3 = *reinterpret_cast<const float4*>(wp_c + 7 * 64);
            #pragma unroll
            for (int r = 0; r < 7; r++) {
                float4 x = *reinterpret_cast<const float4*>(xb + r * 256 + 4);
                acc[r][0] = fmaf(x.x, w0.x, acc[r][0]);
                acc[r][1] = fmaf(x.x, w0.y, acc[r][1]);
                acc[r][2] = fmaf(x.x, w0.z, acc[r][2]);
                acc[r][3] = fmaf(x.x, w0.w, acc[r][3]);
                acc[r][0] = fmaf(x.y, w1.x, acc[r][0]);
                acc[r][1] = fmaf(x.y, w1.y, acc[r][1]);
                acc[r][2] = fmaf(x.y, w1.z, acc[r][2]);
                acc[r][3] = fmaf(x.y, w1.w, acc[r][3]);
                acc[r][0] = fmaf(x.z, w2v.x, acc[r][0]);
                acc[r][1] = fmaf(x.z, w2v.y, acc[r][1]);
                acc[r][2] = fmaf(x.z, w2v.z, acc[r][2]);
                acc[r][3] = fmaf(x.z, w2v.w, acc[r][3]);
                acc[r][0] = fmaf(x.w, w3.x, acc[r][0]);
                acc[r][1] = fmaf(x.w, w3.y, acc[r][1]);
                acc[r][2] = fmaf(x.w, w3.z, acc[r][2]);
                acc[r][3] = fmaf(x.w, w3.w, acc[r][3]);
            }
        }

        #pragma unroll
        for (int r = 0; r < 7; r++)
            #pragma unroll
            for (int j = 0; j < 4; j++)
                acc[r][j] += __shfl_xor_sync(0xffffffffu, acc[r][j], 16);

        if (half == 0) {
            float* pp = sm + P_OFF + es * 952 + (rg * 7) * 68 + hq;
            #pragma unroll
            for (int r = 0; r < 7; r++)
                *reinterpret_cast<float4*>(pp + r * 68) =
                    make_float4(acc[r][0], acc[r][1], acc[r][2], acc[r][3]);
        }
    }
    __syncthreads();

    // reduce 16 partials -> g_ctxT (t-major thread map: coalesced stores)
    if (tid < 896) {
        const int h = tid / 14, r = tid - h * 14;
        float s = 0.f;
        #pragma unroll
        for (int e16 = 0; e16 < 16; e16++)
            s += sm[P_OFF + e16 * 952 + r * 68 + h];
        s += b1i[h];
        const int t = d0 + r;
        if (t < 512) g_ctxT[((b << 6) + h) * 512 + t] = s;
    }
    __syncthreads();
    // release: CTA's ctxT stores happen-before this (bar.sync + cumulativity)
    if (tid == 0) red_release_add(&g_done[b * 37 + ti], 1u);

    // ===================== divergence: producers / consumers ===============
    if (wid >= 16) {
        // ---------------- producers: dec projection, 4 h-chunks ------------
        const int p     = wid - 16;               // 0..15: e-range [32p,32p+32)
        const int phalf = lane >> 4;              // 16-e subrange
        const int hl    = lane & 15;              // h within chunk
        const int q     = tid - 512;              // producer linear id
        const float* xb = sm + DT_OFF + p * 32 + phalf * 16;

        #pragma unroll 1
        for (int c = 0; c < 4; c++) {
            const int hbase = c << 4;
            float acc[14];
            #pragma unroll
            for (int r = 0; r < 14; r++) acc[r] = 0.f;

            const float* wp = W1h + (size_t)(p * 32 + phalf * 16) * 64 + hbase + hl;
            #pragma unroll
            for (int ec = 0; ec < 16; ec += 4) {
                float w0 = wp[(ec + 0) * 64];
                float w1 = wp[(ec + 1) * 64];
                float w2v = wp[(ec + 2) * 64];
                float w3 = wp[(ec + 3) * 64];
                #pragma unroll
                for (int r = 0; r < 14; r++) {
                    float4 x = *reinterpret_cast<const float4*>(xb + r * 512 + ec);
                    acc[r] = fmaf(x.x, w0,
                             fmaf(x.y, w1,
                             fmaf(x.z, w2v,
                             fmaf(x.w, w3, acc[r]))));
                }
            }
            #pragma unroll
            for (int r = 0; r < 14; r++)
                acc[r] += __shfl_xor_sync(0xffffffffu, acc[r], 16);

            float* pb = sm + P_OFF + (c & 1) * 3584;   // ping-pong partials
            if (phalf == 0) {
                #pragma unroll
                for (int r = 0; r < 14; r++)
                    pb[p * 224 + r * 16 + hl] = acc[r];
            }
            bar_sync(6, 512);                          // producer-only
            if (q < 224) {
                const int r = q >> 4, hh = q & 15;
                float s = 0.f;
                #pragma unroll
                for (int p16 = 0; p16 < 16; p16++) s += pb[p16 * 224 + q];
                dec_sh[(r << 6) + hbase + hh] = s + b1h[hbase + hh];
            }
            bar_arrive(1 + c, 1024);                   // publish chunk c
        }
        // producers done; exit
    } else {
        // ---------------- consumers: tanh-score + softmax ------------------
        const int t = tid;                             // 0..511
        // each lane waits only for ITS source block's ctxT columns
        {
            const unsigned target = gen_sh + 1u;
            const unsigned* flag = &g_done[b * 37 + (t / 14)];
            while (ld_acquire(flag) < target) {}
        }

        const float* cptr = g_ctxT + (size_t)(b << 6) * 512 + t;

        float acc[14];
        #pragma unroll
        for (int d = 0; d < 14; d++) acc[d] = 0.f;

        float c0 = cptr[0 * 512];
        float c1 = cptr[1 * 512];
        float c2 = cptr[2 * 512];
        float c3 = cptr[3 * 512];

        #pragma unroll 1
        for (int c = 0; c < 4; c++) {
            bar_sync(1 + c, 1024);                     // wait dec chunk c
            #pragma unroll
            for (int hh = 0; hh < 16; hh += 4) {
                const int h = (c << 4) + hh;
                const int hn = (h + 4) & 63;
                float n0 = cptr[(hn + 0) * 512];
                float n1 = cptr[(hn + 1) * 512];
                float n2 = cptr[(hn + 2) * 512];
                float n3 = cptr[(hn + 3) * 512];

                float4 w4 = *reinterpret_cast<const float4*>(&w2_sh[h]);
                #pragma unroll
                for (int d = 0; d < 14; d++) {
                    float4 dv = *reinterpret_cast<const float4*>(&dec_sh[(d << 6) + h]);
                    acc[d] = fmaf(w4.x, tanh_approx(dv.x + c0), acc[d]);
                    acc[d] = fmaf(w4.y, tanh_approx(dv.y + c1), acc[d]);
                    acc[d] = fmaf(w4.z, tanh_approx(dv.z + c2), acc[d]);
                    acc[d] = fmaf(w4.w, tanh_approx(dv.w + c3), acc[d]);
                }
                c0 = n0; c1 = n1; c2 = n2; c3 = n3;
            }
        }

        // softmax over t (acc in log2 domain; scores bounded => no max-shift)
        float ex[14];
        #pragma unroll
        for (int d = 0; d < 14; d++) {
            float e = ex2_approx(acc[d]);
            ex[d] = e;
            float s = e;
            #pragma unroll
            for (int off = 16; off; off >>= 1)
                s += __shfl_xor_sync(0xffffffffu, s, off);
            if (lane == 0) red[d * 16 + wid] = s;
        }
        bar_sync(5, 512);
        if (wid < 14) {
            float v = (lane < 16) ? red[wid * 16 + lane] : 0.f;
            #pragma unroll
            for (int off = 8; off; off >>= 1)
                v += __shfl_xor_sync(0xffffffffu, v, off);
            if (lane == 0) inv_sh[wid] = 1.0f / v;
        }
        bar_sync(5, 512);
        #pragma unroll
        for (int d = 0; d < 14; d++) {
            if (d0 + d < 512)
                out[((size_t)(b << 9) + d0 + d) * 512 + t] = ex[d] * inv_sh[d];
        }
    }
}

// ---------------------------------------------------------------------------
extern "C" void kernel_launch(void* const* d_in, const int* in_sizes, int n_in,
                              void* d_out, int out_size)
{
    const float* ctx  = (const float*)d_in[0];
    const float* dec  = (const float*)d_in[1];
    const float* W1i  = (const float*)d_in[2];
    const float* b1i  = (const float*)d_in[3];
    const float* W1h  = (const float*)d_in[4];
    const float* b1h  = (const float*)d_in[5];
    const float* w2   = (const float*)d_in[6];
    float* out = (float*)d_out;

    const int smem_bytes = SM_FLOATS * sizeof(float);   // ~104 KB
    cudaFuncSetAttribute(fused_kernel,
                         cudaFuncAttributeMaxDynamicSharedMemorySize,
                         smem_bytes);
    fused_kernel<<<148, 1024, smem_bytes>>>(ctx, dec, W1i, b1i, W1h, b1h, w2, out);
}